// round 13
// baseline (speedup 1.0000x reference)
#include <cuda_runtime.h>
#include <cuda_bf16.h>
#include <cuda_fp16.h>
#include <cstdint>

#define D        128
#define D4       32
#define MAXN     100000
#define MAXE     640000
#define TILE_M   128
#define ASTRIDE  136   // bf16 elems per smem row (272B: 16B-aligned, conflict-free ldmatrix)

#define TILE_ELEMS (128 * ASTRIDE)
#define WB_ELEMS   (2 * TILE_ELEMS)         // hi + lo per matrix
#define WB_BYTES   (WB_ELEMS * 2)           // 69632 bytes

// Scratch (allocation-free rule: __device__ globals).
__device__ __half g_Kh [(size_t)MAXN * D];      // k, fp16 (feeds sigmoid only)
__device__ __half g_QVh[(size_t)MAXN * 2 * D];  // per node: q[128] | v[128], fp16
__device__ __nv_bfloat16 g_Wb[4 * WB_ELEMS];
__device__ int g_srcA[MAXE];
__device__ int g_dstA[MAXE];
__device__ int g_ss  [MAXE];                    // src sorted by dst
__device__ int g_cnt [MAXN];
__device__ int g_off [MAXN + 1];
__device__ int g_cur [MAXN];
__device__ int g_bsum[128];

// smem layout in bf16 elements
#define SM_A_HI  0
#define SM_A_LO  TILE_ELEMS
#define SM_B0    (2 * TILE_ELEMS)
#define SM_B1    (4 * TILE_ELEMS)
#define SM_BYTES      (6 * TILE_ELEMS * 2)   // KQV kernel: A hi/lo + 2 B buffers
#define SM_BYTES_SKIP (4 * TILE_ELEMS * 2)   // skip kernel: A hi/lo + 1 B buffer

__device__ __forceinline__ uint32_t smem_u32(const void* p) {
    uint32_t a;
    asm("{ .reg .u64 t; cvta.to.shared.u64 t, %1; cvt.u32.u64 %0, t; }"
        : "=r"(a) : "l"(p));
    return a;
}
__device__ __forceinline__ uint32_t pack2(float a, float b) {
    __nv_bfloat162 t = __floats2bfloat162_rn(a, b);
    return *reinterpret_cast<uint32_t*>(&t);
}
__device__ __forceinline__ float bf16_residual(float v) {
    return v - __bfloat162float(__float2bfloat16_rn(v));
}
__device__ __forceinline__ void ldsm_x4(uint32_t* r, uint32_t addr) {
    asm volatile("ldmatrix.sync.aligned.m8n8.x4.shared.b16 {%0,%1,%2,%3}, [%4];"
                 : "=r"(r[0]), "=r"(r[1]), "=r"(r[2]), "=r"(r[3]) : "r"(addr));
}
__device__ __forceinline__ void ldsm_x2(uint32_t* r, uint32_t addr) {
    asm volatile("ldmatrix.sync.aligned.m8n8.x2.shared.b16 {%0,%1}, [%2];"
                 : "=r"(r[0]), "=r"(r[1]) : "r"(addr));
}
__device__ __forceinline__ void mma16816(float* c, const uint32_t* a, const uint32_t* b) {
    asm volatile(
        "mma.sync.aligned.m16n8k16.row.col.f32.bf16.bf16.f32 "
        "{%0,%1,%2,%3}, {%4,%5,%6,%7}, {%8,%9}, {%0,%1,%2,%3};"
        : "+f"(c[0]), "+f"(c[1]), "+f"(c[2]), "+f"(c[3])
        : "r"(a[0]), "r"(a[1]), "r"(a[2]), "r"(a[3]), "r"(b[0]), "r"(b[1]));
}
__device__ __forceinline__ void cpasync16(uint32_t s, const void* g) {
    asm volatile("cp.async.ca.shared.global [%0], [%1], 16;" :: "r"(s), "l"(g));
}
__device__ __forceinline__ float sigmoidf_fast(float z) {
    return __fdividef(1.f, 1.f + __expf(-z));
}

// ---------------------------------------------------------------------------
// zero out (red.add targets must start from 0; out is poisoned by harness)
// ---------------------------------------------------------------------------
__global__ void __launch_bounds__(256) zero_out_kernel(float4* __restrict__ out, int n4)
{
    int i = blockIdx.x * blockDim.x + threadIdx.x;
    if (i < n4) out[i] = make_float4(0.f, 0.f, 0.f, 0.f);
}

// ---------------------------------------------------------------------------
// prep: W -> bf16 hi/lo tiles, coalesced. 32 blocks (8 per matrix).
// ---------------------------------------------------------------------------
__global__ void __launch_bounds__(256) prep_w_kernel(
    const float* __restrict__ Wk, const float* __restrict__ Wq,
    const float* __restrict__ Wv, const float* __restrict__ Wsk)
{
    const int m = blockIdx.x >> 3;
    const int chunk = blockIdx.x & 7;
    const float* W;
    switch (m) {
        case 0:  W = Wk;  break;
        case 1:  W = Wq;  break;
        case 2:  W = Wv;  break;
        default: W = Wsk; break;
    }
    __nv_bfloat16* hi = g_Wb + m * WB_ELEMS;
    __nv_bfloat16* lo = hi + TILE_ELEMS;

    #pragma unroll
    for (int it = 0; it < 2; it++) {
        int pos = chunk * 512 + threadIdx.x + 256 * it;
        int n  = pos >> 5;
        int k0 = (pos & 31) << 2;
        float w0 = W[(size_t)(k0 + 0) * D + n];
        float w1 = W[(size_t)(k0 + 1) * D + n];
        float w2 = W[(size_t)(k0 + 2) * D + n];
        float w3 = W[(size_t)(k0 + 3) * D + n];
        int e = n * ASTRIDE + k0;
        *(uint2*)(hi + e) = make_uint2(pack2(w0, w1), pack2(w2, w3));
        *(uint2*)(lo + e) = make_uint2(pack2(bf16_residual(w0), bf16_residual(w1)),
                                       pack2(bf16_residual(w2), bf16_residual(w3)));
    }
}

// ---------------------------------------------------------------------------
// shared helper: load + convert A (x tile) into smem hi/lo
// ---------------------------------------------------------------------------
__device__ __forceinline__ void load_a_tile(
    __nv_bfloat16* sm, const float* __restrict__ x, int m0, int rem, int tid)
{
    const float4* x4 = (const float4*)(x + (size_t)m0 * D);
    #pragma unroll
    for (int i = 0; i < 16; i++) {
        int idx = tid + 256 * i;
        int row = idx >> 5;
        int k4  = (idx & 31) << 2;
        float4 v = make_float4(0.f, 0.f, 0.f, 0.f);
        if (row < rem) v = x4[idx];
        uint2 hi = make_uint2(pack2(v.x, v.y), pack2(v.z, v.w));
        uint2 lo = make_uint2(pack2(bf16_residual(v.x), bf16_residual(v.y)),
                              pack2(bf16_residual(v.z), bf16_residual(v.w)));
        int e = row * ASTRIDE + k4;
        *(uint2*)(sm + SM_A_HI + e) = hi;
        *(uint2*)(sm + SM_A_LO + e) = lo;
    }
}

// ---------------------------------------------------------------------------
// KQV GEMM: K,Q (2-pass hi/lo) and V (3-pass). Outputs fp16.
// ---------------------------------------------------------------------------
__global__ void __launch_bounds__(256) gemm_kqv_kernel(
    const float* __restrict__ x, int N,
    const float* __restrict__ bk, const float* __restrict__ bq,
    const float* __restrict__ bv)
{
    extern __shared__ __nv_bfloat16 sm[];
    const uint32_t sbase = smem_u32(sm);

    const int tid  = threadIdx.x;
    const int wid  = tid >> 5;
    const int lane = tid & 31;
    const int m0   = blockIdx.x * TILE_M;
    const int rem  = N - m0;

    {
        const char* gsrc = (const char*)g_Wb;
        uint32_t sdst = sbase + SM_B0 * 2;
        #pragma unroll
        for (int i = 0; i < 17; i++) {
            uint32_t off = (uint32_t)(tid + 256 * i) * 16;
            cpasync16(sdst + off, gsrc + off);
        }
        asm volatile("cp.async.commit_group;");
    }

    load_a_tile(sm, x, m0, rem, tid);

    const int mw = (wid & 1) << 6;
    const int nw = (wid >> 1) << 5;
    const int arow = lane & 15;
    const int acol = (lane >> 4) << 3;
    const int brow = lane & 7;
    const int bcol = ((lane >> 3) & 1) << 3;
    const int gid  = lane >> 2;
    const int tg   = lane & 3;

    const float* const bias[3] = { bk, bq, bv };

    #pragma unroll
    for (int mi = 0; mi < 3; mi++) {
        if (mi < 2) {
            const char* gsrc = (const char*)(g_Wb + (mi + 1) * WB_ELEMS);
            uint32_t sdst = sbase + (((mi + 1) & 1) ? SM_B1 : SM_B0) * 2;
            #pragma unroll
            for (int i = 0; i < 17; i++) {
                uint32_t off = (uint32_t)(tid + 256 * i) * 16;
                cpasync16(sdst + off, gsrc + off);
            }
            asm volatile("cp.async.commit_group;");
            asm volatile("cp.async.wait_group 1;");
        } else {
            asm volatile("cp.async.wait_group 0;");
        }
        __syncthreads();

        const uint32_t bHI = sbase + (((mi & 1) ? SM_B1 : SM_B0)) * 2;
        const uint32_t bLO = bHI + TILE_ELEMS * 2;
        const bool fullfix = (mi == 2);   // V gets the Al*Bh pass

        float acc[4][4][4];
        #pragma unroll
        for (int i = 0; i < 4; i++)
            #pragma unroll
            for (int j = 0; j < 4; j++)
                #pragma unroll
                for (int k = 0; k < 4; k++) acc[i][j][k] = 0.f;

        #pragma unroll 1
        for (int ks = 0; ks < 8; ks++) {
            const int kk = ks << 4;
            uint32_t ah[4][4], al[4][4], bh[4][2], bl[4][2];
            #pragma unroll
            for (int mt = 0; mt < 4; mt++) {
                uint32_t off = (uint32_t)((mw + (mt << 4) + arow) * ASTRIDE + kk + acol) * 2;
                ldsm_x4(ah[mt], sbase + SM_A_HI * 2 + off);
                if (fullfix) ldsm_x4(al[mt], sbase + SM_A_LO * 2 + off);
            }
            #pragma unroll
            for (int nt = 0; nt < 4; nt++) {
                uint32_t off = (uint32_t)((nw + (nt << 3) + brow) * ASTRIDE + kk + bcol) * 2;
                ldsm_x2(bh[nt], bHI + off);
                ldsm_x2(bl[nt], bLO + off);
            }
            #pragma unroll
            for (int mt = 0; mt < 4; mt++)
                #pragma unroll
                for (int nt = 0; nt < 4; nt++) {
                    mma16816(acc[mt][nt], ah[mt], bh[nt]);
                    mma16816(acc[mt][nt], ah[mt], bl[nt]);
                    if (fullfix) mma16816(acc[mt][nt], al[mt], bh[nt]);
                }
        }

        // epilogue: add bias; K -> g_Kh, Q/V -> g_QVh (fp16)
        {
            const float* b = bias[mi];
            #pragma unroll
            for (int mt = 0; mt < 4; mt++) {
                #pragma unroll
                for (int nt = 0; nt < 4; nt++) {
                    int col = nw + (nt << 3) + (tg << 1);
                    float2 bb = *(const float2*)(b + col);
                    int r0 = mw + (mt << 4) + gid;
                    int r1 = r0 + 8;
                    float2 u0, u1;
                    u0.x = acc[mt][nt][0] + bb.x; u0.y = acc[mt][nt][1] + bb.y;
                    u1.x = acc[mt][nt][2] + bb.x; u1.y = acc[mt][nt][3] + bb.y;
                    if (mi == 0) {
                        if (m0 + r0 < N)
                            *(__half2*)(g_Kh + (size_t)(m0 + r0) * D + col) =
                                __floats2half2_rn(u0.x, u0.y);
                        if (m0 + r1 < N)
                            *(__half2*)(g_Kh + (size_t)(m0 + r1) * D + col) =
                                __floats2half2_rn(u1.x, u1.y);
                    } else {
                        const int co = (mi == 1) ? 0 : D;   // q at 0, v at 128
                        if (m0 + r0 < N)
                            *(__half2*)(g_QVh + (size_t)(m0 + r0) * 2 * D + co + col) =
                                __floats2half2_rn(u0.x, u0.y);
                        if (m0 + r1 < N)
                            *(__half2*)(g_QVh + (size_t)(m0 + r1) * 2 * D + co + col) =
                                __floats2half2_rn(u1.x, u1.y);
                    }
                }
            }
        }
        __syncthreads();
    }
}

// ---------------------------------------------------------------------------
// Skip GEMM: full 3-pass hi/lo; red.add fp32 into zeroed out (runs
// concurrently with edge_agg, which also red.adds — two commutative adds
// per element, deterministic).
// ---------------------------------------------------------------------------
__global__ void __launch_bounds__(256) gemm_skip_kernel(
    const float* __restrict__ x, int N,
    const float* __restrict__ bsk, float* __restrict__ out)
{
    extern __shared__ __nv_bfloat16 sm[];
    const uint32_t sbase = smem_u32(sm);

    const int tid  = threadIdx.x;
    const int wid  = tid >> 5;
    const int lane = tid & 31;
    const int m0   = blockIdx.x * TILE_M;
    const int rem  = N - m0;

    {
        const char* gsrc = (const char*)(g_Wb + 3 * WB_ELEMS);
        uint32_t sdst = sbase + SM_B0 * 2;
        #pragma unroll
        for (int i = 0; i < 17; i++) {
            uint32_t off = (uint32_t)(tid + 256 * i) * 16;
            cpasync16(sdst + off, gsrc + off);
        }
        asm volatile("cp.async.commit_group;");
    }

    load_a_tile(sm, x, m0, rem, tid);
    asm volatile("cp.async.wait_group 0;");
    __syncthreads();

    const int mw = (wid & 1) << 6;
    const int nw = (wid >> 1) << 5;
    const int arow = lane & 15;
    const int acol = (lane >> 4) << 3;
    const int brow = lane & 7;
    const int bcol = ((lane >> 3) & 1) << 3;
    const int gid  = lane >> 2;
    const int tg   = lane & 3;

    const uint32_t bHI = sbase + SM_B0 * 2;
    const uint32_t bLO = bHI + TILE_ELEMS * 2;

    float acc[4][4][4];
    #pragma unroll
    for (int i = 0; i < 4; i++)
        #pragma unroll
        for (int j = 0; j < 4; j++)
            #pragma unroll
            for (int k = 0; k < 4; k++) acc[i][j][k] = 0.f;

    #pragma unroll 1
    for (int ks = 0; ks < 8; ks++) {
        const int kk = ks << 4;
        uint32_t ah[4][4], al[4][4], bh[4][2], bl[4][2];
        #pragma unroll
        for (int mt = 0; mt < 4; mt++) {
            uint32_t off = (uint32_t)((mw + (mt << 4) + arow) * ASTRIDE + kk + acol) * 2;
            ldsm_x4(ah[mt], sbase + SM_A_HI * 2 + off);
            ldsm_x4(al[mt], sbase + SM_A_LO * 2 + off);
        }
        #pragma unroll
        for (int nt = 0; nt < 4; nt++) {
            uint32_t off = (uint32_t)((nw + (nt << 3) + brow) * ASTRIDE + kk + bcol) * 2;
            ldsm_x2(bh[nt], bHI + off);
            ldsm_x2(bl[nt], bLO + off);
        }
        #pragma unroll
        for (int mt = 0; mt < 4; mt++)
            #pragma unroll
            for (int nt = 0; nt < 4; nt++) {
                mma16816(acc[mt][nt], ah[mt], bh[nt]);
                mma16816(acc[mt][nt], ah[mt], bl[nt]);
                mma16816(acc[mt][nt], al[mt], bh[nt]);
            }
    }

    {
        #pragma unroll
        for (int mt = 0; mt < 4; mt++) {
            #pragma unroll
            for (int nt = 0; nt < 4; nt++) {
                int col = nw + (nt << 3) + (tg << 1);
                float2 bb = *(const float2*)(bsk + col);
                int r0 = mw + (mt << 4) + gid;
                int r1 = r0 + 8;
                float2 u0, u1;
                u0.x = acc[mt][nt][0] + bb.x; u0.y = acc[mt][nt][1] + bb.y;
                u1.x = acc[mt][nt][2] + bb.x; u1.y = acc[mt][nt][3] + bb.y;
                if (m0 + r0 < N) {
                    float* p = out + (size_t)(m0 + r0) * D + col;
                    asm volatile("red.global.add.v2.f32 [%0], {%1, %2};"
                                 :: "l"(p), "f"(u0.x), "f"(u0.y) : "memory");
                }
                if (m0 + r1 < N) {
                    float* p = out + (size_t)(m0 + r1) * D + col;
                    asm volatile("red.global.add.v2.f32 [%0], {%1, %2};"
                                 :: "l"(p), "f"(u1.x), "f"(u1.y) : "memory");
                }
            }
        }
    }
}

// ---------------------------------------------------------------------------
// Sort chain (side stream): zero -> convert+hist -> scan -> apply -> scatter
// ---------------------------------------------------------------------------
__global__ void __launch_bounds__(256) zero_cnt_kernel(int N)
{
    int i = blockIdx.x * blockDim.x + threadIdx.x;
    if (i < N) g_cnt[i] = 0;
}

__global__ void __launch_bounds__(256) convhist_kernel(
    const void* __restrict__ ei_raw, int E)
{
    const int idx  = blockIdx.x * blockDim.x + threadIdx.x;
    const int lane = threadIdx.x & 31;

    const int* raw = (const int*)ei_raw;
    unsigned nz = __ballot_sync(0xffffffffu,
                                (lane < 16) ? (raw[2 * lane + 1] != 0) : false);
    const bool is64 = (nz == 0u);

    if (idx < E) {
        int s, d;
        if (is64) {
            const long long* e64 = (const long long*)ei_raw;
            s = (int)e64[idx];
            d = (int)e64[(size_t)E + idx];
        } else {
            s = raw[idx];
            d = raw[(size_t)E + idx];
        }
        g_srcA[idx] = s;
        g_dstA[idx] = d;
        atomicAdd(&g_cnt[d], 1);
    }
}

__global__ void __launch_bounds__(1024) scan1_kernel(int N)
{
    __shared__ int s[1024];
    const int tid = threadIdx.x;
    const int i = blockIdx.x * 1024 + tid;
    int v = (i < N) ? g_cnt[i] : 0;
    s[tid] = v;
    __syncthreads();
    #pragma unroll
    for (int off = 1; off < 1024; off <<= 1) {
        int t = (tid >= off) ? s[tid - off] : 0;
        __syncthreads();
        s[tid] += t;
        __syncthreads();
    }
    if (i <= N) g_off[i] = s[tid] - v;
    if (tid == 1023) g_bsum[blockIdx.x] = s[1023];
}

__global__ void __launch_bounds__(1024) scan_apply_kernel(int N, int E)
{
    __shared__ int bpre_s;
    const int tid = threadIdx.x;
    if (tid < 32) {
        int v = 0;
        for (int b = tid; b < blockIdx.x; b += 32) v += g_bsum[b];
        #pragma unroll
        for (int o = 16; o > 0; o >>= 1) v += __shfl_down_sync(0xffffffffu, v, o);
        if (tid == 0) bpre_s = v;
    }
    __syncthreads();
    const int bpre = bpre_s;
    const int i = blockIdx.x * 1024 + tid;
    if (i < N) {
        int o = g_off[i] + bpre;
        g_off[i] = o;
        g_cur[i] = o;
    }
    if (i == 0) g_off[N] = E;
}

__global__ void __launch_bounds__(256) scatter_kernel(int E)
{
    int idx = blockIdx.x * blockDim.x + threadIdx.x;
    if (idx < E) {
        int d = g_dstA[idx];
        int p = atomicAdd(&g_cur[d], 1);
        g_ss[p] = g_srcA[idx];
    }
}

// ---------------------------------------------------------------------------
// Aggregate: one warp per dst node, x2 unroll, MUFU sigmoid, fp16 K/QV.
// red.add into zeroed out (concurrent with gemm_skip_kernel's red.add).
// ---------------------------------------------------------------------------
__global__ void __launch_bounds__(256) edge_agg_kernel(int N, float* __restrict__ out)
{
    const int node = (blockIdx.x * blockDim.x + threadIdx.x) >> 5;
    const int lane = threadIdx.x & 31;
    if (node >= N) return;

    const int e0 = g_off[node];
    const int e1 = g_off[node + 1];
    if (e0 == e1) return;

    float4 kd;
    {
        uint2 uk = *(const uint2*)(g_Kh + (size_t)node * D + 4 * lane);
        float2 ka = __half22float2(*(__half2*)&uk.x);
        float2 kb = __half22float2(*(__half2*)&uk.y);
        kd = make_float4(ka.x, ka.y, kb.x, kb.y);
    }
    float4 acc = make_float4(0.f, 0.f, 0.f, 0.f);

    int e = e0;
    #pragma unroll 1
    for (; e + 2 <= e1; e += 2) {
        int s0 = g_ss[e], s1 = g_ss[e + 1];
        const __half* r0 = g_QVh + (size_t)s0 * 2 * D;
        const __half* r1 = g_QVh + (size_t)s1 * 2 * D;
        uint2 uq0 = *(const uint2*)(r0 + 4 * lane);
        uint2 uv0 = *(const uint2*)(r0 + D + 4 * lane);
        uint2 uq1 = *(const uint2*)(r1 + 4 * lane);
        uint2 uv1 = *(const uint2*)(r1 + D + 4 * lane);
        float2 qa0 = __half22float2(*(__half2*)&uq0.x), qb0 = __half22float2(*(__half2*)&uq0.y);
        float2 va0 = __half22float2(*(__half2*)&uv0.x), vb0 = __half22float2(*(__half2*)&uv0.y);
        float2 qa1 = __half22float2(*(__half2*)&uq1.x), qb1 = __half22float2(*(__half2*)&uq1.y);
        float2 va1 = __half22float2(*(__half2*)&uv1.x), vb1 = __half22float2(*(__half2*)&uv1.y);
        acc.x += va0.x * sigmoidf_fast(kd.x + qa0.x) + va1.x * sigmoidf_fast(kd.x + qa1.x);
        acc.y += va0.y * sigmoidf_fast(kd.y + qa0.y) + va1.y * sigmoidf_fast(kd.y + qa1.y);
        acc.z += vb0.x * sigmoidf_fast(kd.z + qb0.x) + vb1.x * sigmoidf_fast(kd.z + qb1.x);
        acc.w += vb0.y * sigmoidf_fast(kd.w + qb0.y) + vb1.y * sigmoidf_fast(kd.w + qb1.y);
    }
    if (e < e1) {
        int s0 = g_ss[e];
        const __half* r0 = g_QVh + (size_t)s0 * 2 * D;
        uint2 uq0 = *(const uint2*)(r0 + 4 * lane);
        uint2 uv0 = *(const uint2*)(r0 + D + 4 * lane);
        float2 qa0 = __half22float2(*(__half2*)&uq0.x), qb0 = __half22float2(*(__half2*)&uq0.y);
        float2 va0 = __half22float2(*(__half2*)&uv0.x), vb0 = __half22float2(*(__half2*)&uv0.y);
        acc.x += va0.x * sigmoidf_fast(kd.x + qa0.x);
        acc.y += va0.y * sigmoidf_fast(kd.y + qa0.y);
        acc.z += vb0.x * sigmoidf_fast(kd.z + qb0.x);
        acc.w += vb0.y * sigmoidf_fast(kd.w + qb0.y);
    }

    float* p = out + (size_t)node * D + lane * 4;
    asm volatile("red.global.add.v4.f32 [%0], {%1, %2, %3, %4};"
                 :: "l"(p), "f"(acc.x), "f"(acc.y), "f"(acc.z), "f"(acc.w)
                 : "memory");
}

// ---------------------------------------------------------------------------
extern "C" void kernel_launch(void* const* d_in, const int* in_sizes, int n_in,
                              void* d_out, int out_size)
{
    const float* x    = (const float*)d_in[0];
    const void*  ei   = d_in[1];
    const float* Wk   = (const float*)d_in[3];
    const float* bk   = (const float*)d_in[4];
    const float* Wq   = (const float*)d_in[5];
    const float* bq   = (const float*)d_in[6];
    const float* Wv   = (const float*)d_in[7];
    const float* bv   = (const float*)d_in[8];
    const float* Wsk  = (const float*)d_in[9];
    const float* bias = (const float*)d_in[10];
    float* out = (float*)d_out;

    const int N = in_sizes[0] / D;
    const int E = in_sizes[1] / 2;

    cudaFuncSetAttribute(gemm_kqv_kernel,
                         cudaFuncAttributeMaxDynamicSharedMemorySize, SM_BYTES);
    cudaFuncSetAttribute(gemm_skip_kernel,
                         cudaFuncAttributeMaxDynamicSharedMemorySize, SM_BYTES_SKIP);

    cudaStream_t s2;
    cudaStreamCreateWithFlags(&s2, cudaStreamNonBlocking);
    cudaEvent_t evFork, evPrep, evChain, evSkip;
    cudaEventCreateWithFlags(&evFork,  cudaEventDisableTiming);
    cudaEventCreateWithFlags(&evPrep,  cudaEventDisableTiming);
    cudaEventCreateWithFlags(&evChain, cudaEventDisableTiming);
    cudaEventCreateWithFlags(&evSkip,  cudaEventDisableTiming);

    cudaEventRecord(evFork, 0);
    cudaStreamWaitEvent(s2, evFork, 0);

    // branch B (side stream): edge sort chain, then skip-gemm (after prep+zero)
    zero_cnt_kernel<<<(N + 255) / 256, 256, 0, s2>>>(N);
    convhist_kernel<<<(E + 255) / 256, 256, 0, s2>>>(ei, E);
    const int nb = (N + 1023) / 1024;
    scan1_kernel<<<nb, 1024, 0, s2>>>(N);
    scan_apply_kernel<<<nb, 1024, 0, s2>>>(N, E);
    scatter_kernel<<<(E + 255) / 256, 256, 0, s2>>>(E);
    cudaEventRecord(evChain, s2);

    // branch A (main stream): zero out, prep, KQV projections
    const int n4 = (N * D) / 4;
    zero_out_kernel<<<(n4 + 255) / 256, 256>>>((float4*)out, n4);
    prep_w_kernel<<<32, 256>>>(Wk, Wq, Wv, Wsk);
    cudaEventRecord(evPrep, 0);
    gemm_kqv_kernel<<<(N + TILE_M - 1) / TILE_M, 256, SM_BYTES>>>(
        x, N, bk, bq, bv);

    // side stream: skip-gemm (needs prep + zeroed out; overlaps with agg)
    cudaStreamWaitEvent(s2, evPrep, 0);
    gemm_skip_kernel<<<(N + TILE_M - 1) / TILE_M, 256, SM_BYTES_SKIP, s2>>>(
        x, N, bias, out);
    cudaEventRecord(evSkip, s2);

    // main stream: aggregate after sort chain + KQV
    cudaStreamWaitEvent(0, evChain, 0);
    edge_agg_kernel<<<(N * 32 + 255) / 256, 256>>>(N, out);
    cudaStreamWaitEvent(0, evSkip, 0);

    cudaEventDestroy(evFork);
    cudaEventDestroy(evPrep);
    cudaEventDestroy(evChain);
    cudaEventDestroy(evSkip);
    cudaStreamDestroy(s2);
}

// round 14
// speedup vs baseline: 1.0100x; 1.0100x over previous
#include <cuda_runtime.h>
#include <cuda_bf16.h>
#include <cuda_fp16.h>
#include <cstdint>

#define D        128
#define D4       32
#define MAXN     100000
#define MAXE     640000
#define TILE_M   128
#define ASTRIDE  136   // bf16 elems per smem row (272B: 16B-aligned, conflict-free ldmatrix)
#define EPW      8     // edges per warp in balanced aggregation

#define TILE_ELEMS (128 * ASTRIDE)
#define WB_ELEMS   (2 * TILE_ELEMS)         // hi + lo per matrix
#define WB_BYTES   (WB_ELEMS * 2)           // 69632 bytes

// Scratch (allocation-free rule: __device__ globals).
__device__ __half g_Kh [(size_t)MAXN * D];      // k, fp16 (feeds sigmoid only)
__device__ __half g_QVh[(size_t)MAXN * 2 * D];  // per node: q[128] | v[128], fp16
__device__ __nv_bfloat16 g_Wb[4 * WB_ELEMS];
__device__ int g_srcA[MAXE];
__device__ int g_dstA[MAXE];
__device__ int g_ss  [MAXE];                    // src sorted by dst
__device__ int g_ds  [MAXE];                    // dst sorted (same order)
__device__ int g_cnt [MAXN];
__device__ int g_off [MAXN + 1];
__device__ int g_cur [MAXN];
__device__ int g_bsum[128];

// smem layout in bf16 elements
#define SM_A_HI  0
#define SM_A_LO  TILE_ELEMS
#define SM_B0    (2 * TILE_ELEMS)
#define SM_B1    (4 * TILE_ELEMS)
#define SM_BYTES (6 * TILE_ELEMS * 2)

__device__ __forceinline__ uint32_t smem_u32(const void* p) {
    uint32_t a;
    asm("{ .reg .u64 t; cvta.to.shared.u64 t, %1; cvt.u32.u64 %0, t; }"
        : "=r"(a) : "l"(p));
    return a;
}
__device__ __forceinline__ uint32_t pack2(float a, float b) {
    __nv_bfloat162 t = __floats2bfloat162_rn(a, b);
    return *reinterpret_cast<uint32_t*>(&t);
}
__device__ __forceinline__ float bf16_residual(float v) {
    return v - __bfloat162float(__float2bfloat16_rn(v));
}
__device__ __forceinline__ void ldsm_x4(uint32_t* r, uint32_t addr) {
    asm volatile("ldmatrix.sync.aligned.m8n8.x4.shared.b16 {%0,%1,%2,%3}, [%4];"
                 : "=r"(r[0]), "=r"(r[1]), "=r"(r[2]), "=r"(r[3]) : "r"(addr));
}
__device__ __forceinline__ void ldsm_x2(uint32_t* r, uint32_t addr) {
    asm volatile("ldmatrix.sync.aligned.m8n8.x2.shared.b16 {%0,%1}, [%2];"
                 : "=r"(r[0]), "=r"(r[1]) : "r"(addr));
}
__device__ __forceinline__ void mma16816(float* c, const uint32_t* a, const uint32_t* b) {
    asm volatile(
        "mma.sync.aligned.m16n8k16.row.col.f32.bf16.bf16.f32 "
        "{%0,%1,%2,%3}, {%4,%5,%6,%7}, {%8,%9}, {%0,%1,%2,%3};"
        : "+f"(c[0]), "+f"(c[1]), "+f"(c[2]), "+f"(c[3])
        : "r"(a[0]), "r"(a[1]), "r"(a[2]), "r"(a[3]), "r"(b[0]), "r"(b[1]));
}
__device__ __forceinline__ void cpasync16(uint32_t s, const void* g) {
    asm volatile("cp.async.ca.shared.global [%0], [%1], 16;" :: "r"(s), "l"(g));
}
__device__ __forceinline__ float sigmoidf_fast(float z) {
    return __fdividef(1.f, 1.f + __expf(-z));
}

// ---------------------------------------------------------------------------
// prep: W -> bf16 hi/lo tiles, coalesced. 32 blocks (8 per matrix).
// ---------------------------------------------------------------------------
__global__ void __launch_bounds__(256) prep_w_kernel(
    const float* __restrict__ Wk, const float* __restrict__ Wq,
    const float* __restrict__ Wv, const float* __restrict__ Wsk)
{
    const int m = blockIdx.x >> 3;
    const int chunk = blockIdx.x & 7;
    const float* W;
    switch (m) {
        case 0:  W = Wk;  break;
        case 1:  W = Wq;  break;
        case 2:  W = Wv;  break;
        default: W = Wsk; break;
    }
    __nv_bfloat16* hi = g_Wb + m * WB_ELEMS;
    __nv_bfloat16* lo = hi + TILE_ELEMS;

    #pragma unroll
    for (int it = 0; it < 2; it++) {
        int pos = chunk * 512 + threadIdx.x + 256 * it;
        int n  = pos >> 5;
        int k0 = (pos & 31) << 2;
        float w0 = W[(size_t)(k0 + 0) * D + n];
        float w1 = W[(size_t)(k0 + 1) * D + n];
        float w2 = W[(size_t)(k0 + 2) * D + n];
        float w3 = W[(size_t)(k0 + 3) * D + n];
        int e = n * ASTRIDE + k0;
        *(uint2*)(hi + e) = make_uint2(pack2(w0, w1), pack2(w2, w3));
        *(uint2*)(lo + e) = make_uint2(pack2(bf16_residual(w0), bf16_residual(w1)),
                                       pack2(bf16_residual(w2), bf16_residual(w3)));
    }
}

// ---------------------------------------------------------------------------
// Fused HMMA GEMM (R12 form). bf16 hi/lo split:
//   K, Q  : 2 passes — x-rounding damped by sigmoid
//   V, skip: 3 passes — linear in output
// K/Q/V stored fp16; skip stored fp32 into out (plain store).
// ---------------------------------------------------------------------------
__global__ void __launch_bounds__(256) gemm_fused_kernel(
    const float* __restrict__ x, int N,
    const float* __restrict__ bk, const float* __restrict__ bq,
    const float* __restrict__ bv, const float* __restrict__ bsk,
    float* __restrict__ out)
{
    extern __shared__ __nv_bfloat16 sm[];
    const uint32_t sbase = smem_u32(sm);

    const int tid  = threadIdx.x;
    const int wid  = tid >> 5;
    const int lane = tid & 31;
    const int m0   = blockIdx.x * TILE_M;
    const int rem  = N - m0;

    {
        const char* gsrc = (const char*)g_Wb;
        uint32_t sdst = sbase + SM_B0 * 2;
        #pragma unroll
        for (int i = 0; i < 17; i++) {
            uint32_t off = (uint32_t)(tid + 256 * i) * 16;
            cpasync16(sdst + off, gsrc + off);
        }
        asm volatile("cp.async.commit_group;");
    }

    {
        const float4* x4 = (const float4*)(x + (size_t)m0 * D);
        #pragma unroll
        for (int i = 0; i < 16; i++) {
            int idx = tid + 256 * i;
            int row = idx >> 5;
            int k4  = (idx & 31) << 2;
            float4 v = make_float4(0.f, 0.f, 0.f, 0.f);
            if (row < rem) v = x4[idx];
            uint2 hi = make_uint2(pack2(v.x, v.y), pack2(v.z, v.w));
            uint2 lo = make_uint2(pack2(bf16_residual(v.x), bf16_residual(v.y)),
                                  pack2(bf16_residual(v.z), bf16_residual(v.w)));
            int e = row * ASTRIDE + k4;
            *(uint2*)(sm + SM_A_HI + e) = hi;
            *(uint2*)(sm + SM_A_LO + e) = lo;
        }
    }

    const int mw = (wid & 1) << 6;
    const int nw = (wid >> 1) << 5;
    const int arow = lane & 15;
    const int acol = (lane >> 4) << 3;
    const int brow = lane & 7;
    const int bcol = ((lane >> 3) & 1) << 3;
    const int gid  = lane >> 2;
    const int tg   = lane & 3;

    const float* const bias[4] = { bk, bq, bv, bsk };

    #pragma unroll
    for (int mi = 0; mi < 4; mi++) {
        if (mi < 3) {
            const char* gsrc = (const char*)(g_Wb + (mi + 1) * WB_ELEMS);
            uint32_t sdst = sbase + (((mi + 1) & 1) ? SM_B1 : SM_B0) * 2;
            #pragma unroll
            for (int i = 0; i < 17; i++) {
                uint32_t off = (uint32_t)(tid + 256 * i) * 16;
                cpasync16(sdst + off, gsrc + off);
            }
            asm volatile("cp.async.commit_group;");
            asm volatile("cp.async.wait_group 1;");
        } else {
            asm volatile("cp.async.wait_group 0;");
        }
        __syncthreads();

        const uint32_t bHI = sbase + (((mi & 1) ? SM_B1 : SM_B0)) * 2;
        const uint32_t bLO = bHI + TILE_ELEMS * 2;
        const bool fullfix = (mi >= 2);   // V, skip get the Al*Bh pass

        float acc[4][4][4];
        #pragma unroll
        for (int i = 0; i < 4; i++)
            #pragma unroll
            for (int j = 0; j < 4; j++)
                #pragma unroll
                for (int k = 0; k < 4; k++) acc[i][j][k] = 0.f;

        #pragma unroll 1
        for (int ks = 0; ks < 8; ks++) {
            const int kk = ks << 4;
            uint32_t ah[4][4], al[4][4], bh[4][2], bl[4][2];
            #pragma unroll
            for (int mt = 0; mt < 4; mt++) {
                uint32_t off = (uint32_t)((mw + (mt << 4) + arow) * ASTRIDE + kk + acol) * 2;
                ldsm_x4(ah[mt], sbase + SM_A_HI * 2 + off);
                if (fullfix) ldsm_x4(al[mt], sbase + SM_A_LO * 2 + off);
            }
            #pragma unroll
            for (int nt = 0; nt < 4; nt++) {
                uint32_t off = (uint32_t)((nw + (nt << 3) + brow) * ASTRIDE + kk + bcol) * 2;
                ldsm_x2(bh[nt], bHI + off);
                ldsm_x2(bl[nt], bLO + off);
            }
            #pragma unroll
            for (int mt = 0; mt < 4; mt++)
                #pragma unroll
                for (int nt = 0; nt < 4; nt++) {
                    mma16816(acc[mt][nt], ah[mt], bh[nt]);
                    mma16816(acc[mt][nt], ah[mt], bl[nt]);
                    if (fullfix) mma16816(acc[mt][nt], al[mt], bh[nt]);
                }
        }

        // epilogue: add bias; K/Q/V -> fp16, skip -> fp32 into out
        {
            const float* b = bias[mi];
            #pragma unroll
            for (int mt = 0; mt < 4; mt++) {
                #pragma unroll
                for (int nt = 0; nt < 4; nt++) {
                    int col = nw + (nt << 3) + (tg << 1);
                    float2 bb = *(const float2*)(b + col);
                    int r0 = mw + (mt << 4) + gid;
                    int r1 = r0 + 8;
                    float2 u0, u1;
                    u0.x = acc[mt][nt][0] + bb.x; u0.y = acc[mt][nt][1] + bb.y;
                    u1.x = acc[mt][nt][2] + bb.x; u1.y = acc[mt][nt][3] + bb.y;
                    if (mi == 3) {
                        if (m0 + r0 < N) *(float2*)(out + (size_t)(m0 + r0) * D + col) = u0;
                        if (m0 + r1 < N) *(float2*)(out + (size_t)(m0 + r1) * D + col) = u1;
                    } else if (mi == 0) {
                        if (m0 + r0 < N)
                            *(__half2*)(g_Kh + (size_t)(m0 + r0) * D + col) =
                                __floats2half2_rn(u0.x, u0.y);
                        if (m0 + r1 < N)
                            *(__half2*)(g_Kh + (size_t)(m0 + r1) * D + col) =
                                __floats2half2_rn(u1.x, u1.y);
                    } else {
                        const int co = (mi == 1) ? 0 : D;   // q at 0, v at 128
                        if (m0 + r0 < N)
                            *(__half2*)(g_QVh + (size_t)(m0 + r0) * 2 * D + co + col) =
                                __floats2half2_rn(u0.x, u0.y);
                        if (m0 + r1 < N)
                            *(__half2*)(g_QVh + (size_t)(m0 + r1) * 2 * D + co + col) =
                                __floats2half2_rn(u1.x, u1.y);
                    }
                }
            }
        }
        __syncthreads();
    }
}

// ---------------------------------------------------------------------------
// Sort chain (side stream): zero -> convert+hist -> scan -> apply -> scatter
// ---------------------------------------------------------------------------
__global__ void __launch_bounds__(256) zero_cnt_kernel(int N)
{
    int i = blockIdx.x * blockDim.x + threadIdx.x;
    if (i < N) g_cnt[i] = 0;
}

__global__ void __launch_bounds__(256) convhist_kernel(
    const void* __restrict__ ei_raw, int E)
{
    const int idx  = blockIdx.x * blockDim.x + threadIdx.x;
    const int lane = threadIdx.x & 31;

    const int* raw = (const int*)ei_raw;
    unsigned nz = __ballot_sync(0xffffffffu,
                                (lane < 16) ? (raw[2 * lane + 1] != 0) : false);
    const bool is64 = (nz == 0u);

    if (idx < E) {
        int s, d;
        if (is64) {
            const long long* e64 = (const long long*)ei_raw;
            s = (int)e64[idx];
            d = (int)e64[(size_t)E + idx];
        } else {
            s = raw[idx];
            d = raw[(size_t)E + idx];
        }
        g_srcA[idx] = s;
        g_dstA[idx] = d;
        atomicAdd(&g_cnt[d], 1);
    }
}

__global__ void __launch_bounds__(1024) scan1_kernel(int N)
{
    __shared__ int s[1024];
    const int tid = threadIdx.x;
    const int i = blockIdx.x * 1024 + tid;
    int v = (i < N) ? g_cnt[i] : 0;
    s[tid] = v;
    __syncthreads();
    #pragma unroll
    for (int off = 1; off < 1024; off <<= 1) {
        int t = (tid >= off) ? s[tid - off] : 0;
        __syncthreads();
        s[tid] += t;
        __syncthreads();
    }
    if (i <= N) g_off[i] = s[tid] - v;
    if (tid == 1023) g_bsum[blockIdx.x] = s[1023];
}

__global__ void __launch_bounds__(1024) scan_apply_kernel(int N, int E)
{
    __shared__ int bpre_s;
    const int tid = threadIdx.x;
    if (tid < 32) {
        int v = 0;
        for (int b = tid; b < blockIdx.x; b += 32) v += g_bsum[b];
        #pragma unroll
        for (int o = 16; o > 0; o >>= 1) v += __shfl_down_sync(0xffffffffu, v, o);
        if (tid == 0) bpre_s = v;
    }
    __syncthreads();
    const int bpre = bpre_s;
    const int i = blockIdx.x * 1024 + tid;
    if (i < N) {
        int o = g_off[i] + bpre;
        g_off[i] = o;
        g_cur[i] = o;
    }
    if (i == 0) g_off[N] = E;
}

__global__ void __launch_bounds__(256) scatter_kernel(int E)
{
    int idx = blockIdx.x * blockDim.x + threadIdx.x;
    if (idx < E) {
        int d = g_dstA[idx];
        int p = atomicAdd(&g_cur[d], 1);
        g_ss[p] = g_srcA[idx];
        g_ds[p] = d;
    }
}

// ---------------------------------------------------------------------------
// Balanced aggregate: one warp per EPW consecutive sorted edges (uniform
// work; no per-node straggler warps). k reloaded only on dst-run change;
// partial sums flushed via red.add onto out (which already holds skip).
// lane c handles channels [4c, 4c+3].
// ---------------------------------------------------------------------------
__device__ __forceinline__ float4 load_k4(int node, int lane) {
    uint2 uk = *(const uint2*)(g_Kh + (size_t)node * D + 4 * lane);
    float2 ka = __half22float2(*(__half2*)&uk.x);
    float2 kb = __half22float2(*(__half2*)&uk.y);
    return make_float4(ka.x, ka.y, kb.x, kb.y);
}
__device__ __forceinline__ void flush4(float* out, int node, int lane, float4 a) {
    float* p = out + (size_t)node * D + lane * 4;
    asm volatile("red.global.add.v4.f32 [%0], {%1, %2, %3, %4};"
                 :: "l"(p), "f"(a.x), "f"(a.y), "f"(a.z), "f"(a.w)
                 : "memory");
}

__global__ void __launch_bounds__(256) edge_agg_kernel(int E, float* __restrict__ out)
{
    const int w    = (blockIdx.x * blockDim.x + threadIdx.x) >> 5;
    const int lane = threadIdx.x & 31;
    const int base = w * EPW;
    if (base >= E) return;
    const int end = (base + EPW < E) ? base + EPW : E;

    int curd = g_ds[base];
    float4 kd = load_k4(curd, lane);
    float4 acc = make_float4(0.f, 0.f, 0.f, 0.f);

    #pragma unroll 1
    for (int e = base; e < end; e++) {
        int d = g_ds[e];
        if (d != curd) {
            flush4(out, curd, lane, acc);
            acc = make_float4(0.f, 0.f, 0.f, 0.f);
            curd = d;
            kd = load_k4(d, lane);
        }
        int s = g_ss[e];
        const __half* r = g_QVh + (size_t)s * 2 * D;
        uint2 uq = *(const uint2*)(r + 4 * lane);
        uint2 uv = *(const uint2*)(r + D + 4 * lane);
        float2 qa = __half22float2(*(__half2*)&uq.x), qb = __half22float2(*(__half2*)&uq.y);
        float2 va = __half22float2(*(__half2*)&uv.x), vb = __half22float2(*(__half2*)&uv.y);
        acc.x += va.x * sigmoidf_fast(kd.x + qa.x);
        acc.y += va.y * sigmoidf_fast(kd.y + qa.y);
        acc.z += vb.x * sigmoidf_fast(kd.z + qb.x);
        acc.w += vb.y * sigmoidf_fast(kd.w + qb.y);
    }
    flush4(out, curd, lane, acc);
}

// ---------------------------------------------------------------------------
extern "C" void kernel_launch(void* const* d_in, const int* in_sizes, int n_in,
                              void* d_out, int out_size)
{
    const float* x    = (const float*)d_in[0];
    const void*  ei   = d_in[1];
    const float* Wk   = (const float*)d_in[3];
    const float* bk   = (const float*)d_in[4];
    const float* Wq   = (const float*)d_in[5];
    const float* bq   = (const float*)d_in[6];
    const float* Wv   = (const float*)d_in[7];
    const float* bv   = (const float*)d_in[8];
    const float* Wsk  = (const float*)d_in[9];
    const float* bias = (const float*)d_in[10];
    float* out = (float*)d_out;

    const int N = in_sizes[0] / D;
    const int E = in_sizes[1] / 2;

    cudaFuncSetAttribute(gemm_fused_kernel,
                         cudaFuncAttributeMaxDynamicSharedMemorySize, SM_BYTES);

    cudaStream_t s2;
    cudaStreamCreateWithFlags(&s2, cudaStreamNonBlocking);
    cudaEvent_t evFork, evJoin;
    cudaEventCreateWithFlags(&evFork, cudaEventDisableTiming);
    cudaEventCreateWithFlags(&evJoin, cudaEventDisableTiming);

    cudaEventRecord(evFork, 0);
    cudaStreamWaitEvent(s2, evFork, 0);

    // branch B (side stream): edge sort chain
    zero_cnt_kernel<<<(N + 255) / 256, 256, 0, s2>>>(N);
    convhist_kernel<<<(E + 255) / 256, 256, 0, s2>>>(ei, E);
    const int nb = (N + 1023) / 1024;
    scan1_kernel<<<nb, 1024, 0, s2>>>(N);
    scan_apply_kernel<<<nb, 1024, 0, s2>>>(N, E);
    scatter_kernel<<<(E + 255) / 256, 256, 0, s2>>>(E);
    cudaEventRecord(evJoin, s2);

    // branch A (main stream): projections (skip written to out here)
    prep_w_kernel<<<32, 256>>>(Wk, Wq, Wv, Wsk);
    gemm_fused_kernel<<<(N + TILE_M - 1) / TILE_M, 256, SM_BYTES>>>(
        x, N, bk, bq, bv, bias, out);

    // join, then balanced aggregate (red.add onto skip)
    cudaStreamWaitEvent(0, evJoin, 0);
    const int nwarps = (E + EPW - 1) / EPW;
    edge_agg_kernel<<<(nwarps * 32 + 255) / 256, 256>>>(E, out);

    cudaEventDestroy(evFork);
    cudaEventDestroy(evJoin);
    cudaStreamDestroy(s2);
}

// round 15
// speedup vs baseline: 1.0446x; 1.0343x over previous
#include <cuda_runtime.h>
#include <cuda_bf16.h>
#include <cuda_fp16.h>
#include <cstdint>

#define D        128
#define D4       32
#define MAXN     100000
#define MAXE     640000
#define TILE_M   128
#define ASTRIDE  136   // bf16 elems per smem row (272B: 16B-aligned, conflict-free ldmatrix)

#define TILE_ELEMS (128 * ASTRIDE)
#define WB_ELEMS   (2 * TILE_ELEMS)         // hi + lo per matrix
#define WB_BYTES   (WB_ELEMS * 2)           // 69632 bytes

// Scratch (allocation-free rule: __device__ globals).
__device__ __half g_Kh [(size_t)MAXN * D];      // k, fp16 (feeds sigmoid only)
__device__ __half g_QVh[(size_t)MAXN * 2 * D];  // per node: q[128] | v[128], fp16
__device__ __nv_bfloat16 g_Wb[4 * WB_ELEMS];
__device__ int g_srcA[MAXE];
__device__ int g_dstA[MAXE];
__device__ int g_ss  [MAXE];                    // src sorted by dst
__device__ int g_cnt [MAXN];
__device__ int g_off [MAXN + 1];
__device__ int g_cur [MAXN];
__device__ int g_bsum[128];

// smem layout in bf16 elements
#define SM_A_HI  0
#define SM_A_LO  TILE_ELEMS
#define SM_B0    (2 * TILE_ELEMS)
#define SM_B1    (4 * TILE_ELEMS)
#define SM_BYTES (6 * TILE_ELEMS * 2)

__device__ __forceinline__ uint32_t smem_u32(const void* p) {
    uint32_t a;
    asm("{ .reg .u64 t; cvta.to.shared.u64 t, %1; cvt.u32.u64 %0, t; }"
        : "=r"(a) : "l"(p));
    return a;
}
__device__ __forceinline__ uint32_t pack2(float a, float b) {
    __nv_bfloat162 t = __floats2bfloat162_rn(a, b);
    return *reinterpret_cast<uint32_t*>(&t);
}
__device__ __forceinline__ float bf16_residual(float v) {
    return v - __bfloat162float(__float2bfloat16_rn(v));
}
__device__ __forceinline__ void ldsm_x4(uint32_t* r, uint32_t addr) {
    asm volatile("ldmatrix.sync.aligned.m8n8.x4.shared.b16 {%0,%1,%2,%3}, [%4];"
                 : "=r"(r[0]), "=r"(r[1]), "=r"(r[2]), "=r"(r[3]) : "r"(addr));
}
__device__ __forceinline__ void ldsm_x2(uint32_t* r, uint32_t addr) {
    asm volatile("ldmatrix.sync.aligned.m8n8.x2.shared.b16 {%0,%1}, [%2];"
                 : "=r"(r[0]), "=r"(r[1]) : "r"(addr));
}
__device__ __forceinline__ void mma16816(float* c, const uint32_t* a, const uint32_t* b) {
    asm volatile(
        "mma.sync.aligned.m16n8k16.row.col.f32.bf16.bf16.f32 "
        "{%0,%1,%2,%3}, {%4,%5,%6,%7}, {%8,%9}, {%0,%1,%2,%3};"
        : "+f"(c[0]), "+f"(c[1]), "+f"(c[2]), "+f"(c[3])
        : "r"(a[0]), "r"(a[1]), "r"(a[2]), "r"(a[3]), "r"(b[0]), "r"(b[1]));
}
__device__ __forceinline__ void cpasync16(uint32_t s, const void* g) {
    asm volatile("cp.async.ca.shared.global [%0], [%1], 16;" :: "r"(s), "l"(g));
}
__device__ __forceinline__ float sigmoidf_fast(float z) {
    return __fdividef(1.f, 1.f + __expf(-z));
}

// ---------------------------------------------------------------------------
// prep: W -> bf16 hi/lo tiles, coalesced. 32 blocks (8 per matrix).
// ---------------------------------------------------------------------------
__global__ void __launch_bounds__(256) prep_w_kernel(
    const float* __restrict__ Wk, const float* __restrict__ Wq,
    const float* __restrict__ Wv, const float* __restrict__ Wsk)
{
    const int m = blockIdx.x >> 3;
    const int chunk = blockIdx.x & 7;
    const float* W;
    switch (m) {
        case 0:  W = Wk;  break;
        case 1:  W = Wq;  break;
        case 2:  W = Wv;  break;
        default: W = Wsk; break;
    }
    __nv_bfloat16* hi = g_Wb + m * WB_ELEMS;
    __nv_bfloat16* lo = hi + TILE_ELEMS;

    #pragma unroll
    for (int it = 0; it < 2; it++) {
        int pos = chunk * 512 + threadIdx.x + 256 * it;
        int n  = pos >> 5;
        int k0 = (pos & 31) << 2;
        float w0 = W[(size_t)(k0 + 0) * D + n];
        float w1 = W[(size_t)(k0 + 1) * D + n];
        float w2 = W[(size_t)(k0 + 2) * D + n];
        float w3 = W[(size_t)(k0 + 3) * D + n];
        int e = n * ASTRIDE + k0;
        *(uint2*)(hi + e) = make_uint2(pack2(w0, w1), pack2(w2, w3));
        *(uint2*)(lo + e) = make_uint2(pack2(bf16_residual(w0), bf16_residual(w1)),
                                       pack2(bf16_residual(w2), bf16_residual(w3)));
    }
}

// ---------------------------------------------------------------------------
// Fused HMMA GEMM (R12 form). bf16 hi/lo split:
//   K, Q  : 2 passes — x-rounding damped by sigmoid
//   V, skip: 3 passes — linear in output
// K/Q/V stored fp16; skip stored fp32 into out (plain store).
// ---------------------------------------------------------------------------
__global__ void __launch_bounds__(256) gemm_fused_kernel(
    const float* __restrict__ x, int N,
    const float* __restrict__ bk, const float* __restrict__ bq,
    const float* __restrict__ bv, const float* __restrict__ bsk,
    float* __restrict__ out)
{
    extern __shared__ __nv_bfloat16 sm[];
    const uint32_t sbase = smem_u32(sm);

    const int tid  = threadIdx.x;
    const int wid  = tid >> 5;
    const int lane = tid & 31;
    const int m0   = blockIdx.x * TILE_M;
    const int rem  = N - m0;

    {
        const char* gsrc = (const char*)g_Wb;
        uint32_t sdst = sbase + SM_B0 * 2;
        #pragma unroll
        for (int i = 0; i < 17; i++) {
            uint32_t off = (uint32_t)(tid + 256 * i) * 16;
            cpasync16(sdst + off, gsrc + off);
        }
        asm volatile("cp.async.commit_group;");
    }

    {
        const float4* x4 = (const float4*)(x + (size_t)m0 * D);
        #pragma unroll
        for (int i = 0; i < 16; i++) {
            int idx = tid + 256 * i;
            int row = idx >> 5;
            int k4  = (idx & 31) << 2;
            float4 v = make_float4(0.f, 0.f, 0.f, 0.f);
            if (row < rem) v = x4[idx];
            uint2 hi = make_uint2(pack2(v.x, v.y), pack2(v.z, v.w));
            uint2 lo = make_uint2(pack2(bf16_residual(v.x), bf16_residual(v.y)),
                                  pack2(bf16_residual(v.z), bf16_residual(v.w)));
            int e = row * ASTRIDE + k4;
            *(uint2*)(sm + SM_A_HI + e) = hi;
            *(uint2*)(sm + SM_A_LO + e) = lo;
        }
    }

    const int mw = (wid & 1) << 6;
    const int nw = (wid >> 1) << 5;
    const int arow = lane & 15;
    const int acol = (lane >> 4) << 3;
    const int brow = lane & 7;
    const int bcol = ((lane >> 3) & 1) << 3;
    const int gid  = lane >> 2;
    const int tg   = lane & 3;

    const float* const bias[4] = { bk, bq, bv, bsk };

    #pragma unroll
    for (int mi = 0; mi < 4; mi++) {
        if (mi < 3) {
            const char* gsrc = (const char*)(g_Wb + (mi + 1) * WB_ELEMS);
            uint32_t sdst = sbase + (((mi + 1) & 1) ? SM_B1 : SM_B0) * 2;
            #pragma unroll
            for (int i = 0; i < 17; i++) {
                uint32_t off = (uint32_t)(tid + 256 * i) * 16;
                cpasync16(sdst + off, gsrc + off);
            }
            asm volatile("cp.async.commit_group;");
            asm volatile("cp.async.wait_group 1;");
        } else {
            asm volatile("cp.async.wait_group 0;");
        }
        __syncthreads();

        const uint32_t bHI = sbase + (((mi & 1) ? SM_B1 : SM_B0)) * 2;
        const uint32_t bLO = bHI + TILE_ELEMS * 2;
        const bool fullfix = (mi >= 2);   // V, skip get the Al*Bh pass

        float acc[4][4][4];
        #pragma unroll
        for (int i = 0; i < 4; i++)
            #pragma unroll
            for (int j = 0; j < 4; j++)
                #pragma unroll
                for (int k = 0; k < 4; k++) acc[i][j][k] = 0.f;

        #pragma unroll 1
        for (int ks = 0; ks < 8; ks++) {
            const int kk = ks << 4;
            uint32_t ah[4][4], al[4][4], bh[4][2], bl[4][2];
            #pragma unroll
            for (int mt = 0; mt < 4; mt++) {
                uint32_t off = (uint32_t)((mw + (mt << 4) + arow) * ASTRIDE + kk + acol) * 2;
                ldsm_x4(ah[mt], sbase + SM_A_HI * 2 + off);
                if (fullfix) ldsm_x4(al[mt], sbase + SM_A_LO * 2 + off);
            }
            #pragma unroll
            for (int nt = 0; nt < 4; nt++) {
                uint32_t off = (uint32_t)((nw + (nt << 3) + brow) * ASTRIDE + kk + bcol) * 2;
                ldsm_x2(bh[nt], bHI + off);
                ldsm_x2(bl[nt], bLO + off);
            }
            #pragma unroll
            for (int mt = 0; mt < 4; mt++)
                #pragma unroll
                for (int nt = 0; nt < 4; nt++) {
                    mma16816(acc[mt][nt], ah[mt], bh[nt]);
                    mma16816(acc[mt][nt], ah[mt], bl[nt]);
                    if (fullfix) mma16816(acc[mt][nt], al[mt], bh[nt]);
                }
        }

        // epilogue: add bias; K/Q/V -> fp16, skip -> fp32 into out
        {
            const float* b = bias[mi];
            #pragma unroll
            for (int mt = 0; mt < 4; mt++) {
                #pragma unroll
                for (int nt = 0; nt < 4; nt++) {
                    int col = nw + (nt << 3) + (tg << 1);
                    float2 bb = *(const float2*)(b + col);
                    int r0 = mw + (mt << 4) + gid;
                    int r1 = r0 + 8;
                    float2 u0, u1;
                    u0.x = acc[mt][nt][0] + bb.x; u0.y = acc[mt][nt][1] + bb.y;
                    u1.x = acc[mt][nt][2] + bb.x; u1.y = acc[mt][nt][3] + bb.y;
                    if (mi == 3) {
                        if (m0 + r0 < N) *(float2*)(out + (size_t)(m0 + r0) * D + col) = u0;
                        if (m0 + r1 < N) *(float2*)(out + (size_t)(m0 + r1) * D + col) = u1;
                    } else if (mi == 0) {
                        if (m0 + r0 < N)
                            *(__half2*)(g_Kh + (size_t)(m0 + r0) * D + col) =
                                __floats2half2_rn(u0.x, u0.y);
                        if (m0 + r1 < N)
                            *(__half2*)(g_Kh + (size_t)(m0 + r1) * D + col) =
                                __floats2half2_rn(u1.x, u1.y);
                    } else {
                        const int co = (mi == 1) ? 0 : D;   // q at 0, v at 128
                        if (m0 + r0 < N)
                            *(__half2*)(g_QVh + (size_t)(m0 + r0) * 2 * D + co + col) =
                                __floats2half2_rn(u0.x, u0.y);
                        if (m0 + r1 < N)
                            *(__half2*)(g_QVh + (size_t)(m0 + r1) * 2 * D + co + col) =
                                __floats2half2_rn(u1.x, u1.y);
                    }
                }
            }
        }
        __syncthreads();
    }
}

// ---------------------------------------------------------------------------
// Sort chain (side stream): zero -> convert+hist -> scan -> apply -> scatter
// ---------------------------------------------------------------------------
__global__ void __launch_bounds__(256) zero_cnt_kernel(int N)
{
    int i = blockIdx.x * blockDim.x + threadIdx.x;
    if (i < N) g_cnt[i] = 0;
}

__global__ void __launch_bounds__(256) convhist_kernel(
    const void* __restrict__ ei_raw, int E)
{
    const int idx  = blockIdx.x * blockDim.x + threadIdx.x;
    const int lane = threadIdx.x & 31;

    const int* raw = (const int*)ei_raw;
    unsigned nz = __ballot_sync(0xffffffffu,
                                (lane < 16) ? (raw[2 * lane + 1] != 0) : false);
    const bool is64 = (nz == 0u);

    if (idx < E) {
        int s, d;
        if (is64) {
            const long long* e64 = (const long long*)ei_raw;
            s = (int)e64[idx];
            d = (int)e64[(size_t)E + idx];
        } else {
            s = raw[idx];
            d = raw[(size_t)E + idx];
        }
        g_srcA[idx] = s;
        g_dstA[idx] = d;
        atomicAdd(&g_cnt[d], 1);
    }
}

__global__ void __launch_bounds__(1024) scan1_kernel(int N)
{
    __shared__ int s[1024];
    const int tid = threadIdx.x;
    const int i = blockIdx.x * 1024 + tid;
    int v = (i < N) ? g_cnt[i] : 0;
    s[tid] = v;
    __syncthreads();
    #pragma unroll
    for (int off = 1; off < 1024; off <<= 1) {
        int t = (tid >= off) ? s[tid - off] : 0;
        __syncthreads();
        s[tid] += t;
        __syncthreads();
    }
    if (i <= N) g_off[i] = s[tid] - v;
    if (tid == 1023) g_bsum[blockIdx.x] = s[1023];
}

__global__ void __launch_bounds__(1024) scan_apply_kernel(int N, int E)
{
    __shared__ int bpre_s;
    const int tid = threadIdx.x;
    if (tid < 32) {
        int v = 0;
        for (int b = tid; b < blockIdx.x; b += 32) v += g_bsum[b];
        #pragma unroll
        for (int o = 16; o > 0; o >>= 1) v += __shfl_down_sync(0xffffffffu, v, o);
        if (tid == 0) bpre_s = v;
    }
    __syncthreads();
    const int bpre = bpre_s;
    const int i = blockIdx.x * 1024 + tid;
    if (i < N) {
        int o = g_off[i] + bpre;
        g_off[i] = o;
        g_cur[i] = o;
    }
    if (i == 0) g_off[N] = E;
}

__global__ void __launch_bounds__(256) scatter_kernel(int E)
{
    int idx = blockIdx.x * blockDim.x + threadIdx.x;
    if (idx < E) {
        int d = g_dstA[idx];
        int p = atomicAdd(&g_cur[d], 1);
        g_ss[p] = g_srcA[idx];
    }
}

// ---------------------------------------------------------------------------
// Aggregate: one warp per dst node, x2 unroll, MUFU sigmoid, fp16 K/QV.
// Result emitted via red.global.add onto out (already holds skip) — no
// read-modify-write of out in this kernel.
// ---------------------------------------------------------------------------
__global__ void __launch_bounds__(256) edge_agg_kernel(int N, float* __restrict__ out)
{
    const int node = (blockIdx.x * blockDim.x + threadIdx.x) >> 5;
    const int lane = threadIdx.x & 31;
    if (node >= N) return;

    const int e0 = g_off[node];
    const int e1 = g_off[node + 1];
    if (e0 == e1) return;

    float4 kd;
    {
        uint2 uk = *(const uint2*)(g_Kh + (size_t)node * D + 4 * lane);
        float2 ka = __half22float2(*(__half2*)&uk.x);
        float2 kb = __half22float2(*(__half2*)&uk.y);
        kd = make_float4(ka.x, ka.y, kb.x, kb.y);
    }
    float4 acc = make_float4(0.f, 0.f, 0.f, 0.f);

    int e = e0;
    #pragma unroll 1
    for (; e + 2 <= e1; e += 2) {
        int s0 = g_ss[e], s1 = g_ss[e + 1];
        const __half* r0 = g_QVh + (size_t)s0 * 2 * D;
        const __half* r1 = g_QVh + (size_t)s1 * 2 * D;
        uint2 uq0 = *(const uint2*)(r0 + 4 * lane);
        uint2 uv0 = *(const uint2*)(r0 + D + 4 * lane);
        uint2 uq1 = *(const uint2*)(r1 + 4 * lane);
        uint2 uv1 = *(const uint2*)(r1 + D + 4 * lane);
        float2 qa0 = __half22float2(*(__half2*)&uq0.x), qb0 = __half22float2(*(__half2*)&uq0.y);
        float2 va0 = __half22float2(*(__half2*)&uv0.x), vb0 = __half22float2(*(__half2*)&uv0.y);
        float2 qa1 = __half22float2(*(__half2*)&uq1.x), qb1 = __half22float2(*(__half2*)&uq1.y);
        float2 va1 = __half22float2(*(__half2*)&uv1.x), vb1 = __half22float2(*(__half2*)&uv1.y);
        acc.x += va0.x * sigmoidf_fast(kd.x + qa0.x) + va1.x * sigmoidf_fast(kd.x + qa1.x);
        acc.y += va0.y * sigmoidf_fast(kd.y + qa0.y) + va1.y * sigmoidf_fast(kd.y + qa1.y);
        acc.z += vb0.x * sigmoidf_fast(kd.z + qb0.x) + vb1.x * sigmoidf_fast(kd.z + qb1.x);
        acc.w += vb0.y * sigmoidf_fast(kd.w + qb0.y) + vb1.y * sigmoidf_fast(kd.w + qb1.y);
    }
    if (e < e1) {
        int s0 = g_ss[e];
        const __half* r0 = g_QVh + (size_t)s0 * 2 * D;
        uint2 uq0 = *(const uint2*)(r0 + 4 * lane);
        uint2 uv0 = *(const uint2*)(r0 + D + 4 * lane);
        float2 qa0 = __half22float2(*(__half2*)&uq0.x), qb0 = __half22float2(*(__half2*)&uq0.y);
        float2 va0 = __half22float2(*(__half2*)&uv0.x), vb0 = __half22float2(*(__half2*)&uv0.y);
        acc.x += va0.x * sigmoidf_fast(kd.x + qa0.x);
        acc.y += va0.y * sigmoidf_fast(kd.y + qa0.y);
        acc.z += vb0.x * sigmoidf_fast(kd.z + qb0.x);
        acc.w += vb0.y * sigmoidf_fast(kd.w + qb0.y);
    }

    float* p = out + (size_t)node * D + lane * 4;
    asm volatile("red.global.add.v4.f32 [%0], {%1, %2, %3, %4};"
                 :: "l"(p), "f"(acc.x), "f"(acc.y), "f"(acc.z), "f"(acc.w)
                 : "memory");
}

// ---------------------------------------------------------------------------
extern "C" void kernel_launch(void* const* d_in, const int* in_sizes, int n_in,
                              void* d_out, int out_size)
{
    const float* x    = (const float*)d_in[0];
    const void*  ei   = d_in[1];
    const float* Wk   = (const float*)d_in[3];
    const float* bk   = (const float*)d_in[4];
    const float* Wq   = (const float*)d_in[5];
    const float* bq   = (const float*)d_in[6];
    const float* Wv   = (const float*)d_in[7];
    const float* bv   = (const float*)d_in[8];
    const float* Wsk  = (const float*)d_in[9];
    const float* bias = (const float*)d_in[10];
    float* out = (float*)d_out;

    const int N = in_sizes[0] / D;
    const int E = in_sizes[1] / 2;

    cudaFuncSetAttribute(gemm_fused_kernel,
                         cudaFuncAttributeMaxDynamicSharedMemorySize, SM_BYTES);

    cudaStream_t s2;
    cudaStreamCreateWithFlags(&s2, cudaStreamNonBlocking);
    cudaEvent_t evFork, evJoin;
    cudaEventCreateWithFlags(&evFork, cudaEventDisableTiming);
    cudaEventCreateWithFlags(&evJoin, cudaEventDisableTiming);

    cudaEventRecord(evFork, 0);
    cudaStreamWaitEvent(s2, evFork, 0);

    // branch B (side stream): edge sort chain
    zero_cnt_kernel<<<(N + 255) / 256, 256, 0, s2>>>(N);
    convhist_kernel<<<(E + 255) / 256, 256, 0, s2>>>(ei, E);
    const int nb = (N + 1023) / 1024;
    scan1_kernel<<<nb, 1024, 0, s2>>>(N);
    scan_apply_kernel<<<nb, 1024, 0, s2>>>(N, E);
    scatter_kernel<<<(E + 255) / 256, 256, 0, s2>>>(E);
    cudaEventRecord(evJoin, s2);

    // branch A (main stream): projections (skip written to out here)
    prep_w_kernel<<<32, 256>>>(Wk, Wq, Wv, Wsk);
    gemm_fused_kernel<<<(N + TILE_M - 1) / TILE_M, 256, SM_BYTES>>>(
        x, N, bk, bq, bv, bias, out);

    // join, then aggregate (red.add onto skip)
    cudaStreamWaitEvent(0, evJoin, 0);
    edge_agg_kernel<<<(N * 32 + 255) / 256, 256>>>(N, out);

    cudaEventDestroy(evFork);
    cudaEventDestroy(evJoin);
    cudaStreamDestroy(s2);
}

// round 16
// speedup vs baseline: 1.0615x; 1.0161x over previous
#include <cuda_runtime.h>
#include <cuda_bf16.h>
#include <cuda_fp16.h>
#include <cstdint>

#define D        128
#define D4       32
#define MAXN     100000
#define MAXE     640000
#define TILE_M   128
#define ASTRIDE  136   // bf16 elems per smem row (272B: 16B-aligned, conflict-free ldmatrix)

#define TILE_ELEMS (128 * ASTRIDE)
#define WB_ELEMS   (2 * TILE_ELEMS)         // hi + lo per matrix
#define WB_BYTES   (WB_ELEMS * 2)           // 69632 bytes

// Scratch (allocation-free rule: __device__ globals).
__device__ __half g_Kh [(size_t)MAXN * D];      // k, fp16 (feeds sigmoid only)
__device__ __half g_QVh[(size_t)MAXN * 2 * D];  // per node: q[128] | v[128], fp16
__device__ __nv_bfloat16 g_Wb[4 * WB_ELEMS];
__device__ int g_srcA[MAXE];
__device__ int g_dstA[MAXE];
__device__ int g_ss  [MAXE];                    // src sorted by dst
__device__ int g_cnt [MAXN];
__device__ int g_off [MAXN + 1];
__device__ int g_cur [MAXN];
__device__ int g_bsum[128];

// smem layout in bf16 elements
#define SM_A_HI  0
#define SM_A_LO  TILE_ELEMS
#define SM_B0    (2 * TILE_ELEMS)
#define SM_B1    (4 * TILE_ELEMS)
#define SM_BYTES (6 * TILE_ELEMS * 2)

__device__ __forceinline__ uint32_t smem_u32(const void* p) {
    uint32_t a;
    asm("{ .reg .u64 t; cvta.to.shared.u64 t, %1; cvt.u32.u64 %0, t; }"
        : "=r"(a) : "l"(p));
    return a;
}
__device__ __forceinline__ uint32_t pack2(float a, float b) {
    __nv_bfloat162 t = __floats2bfloat162_rn(a, b);
    return *reinterpret_cast<uint32_t*>(&t);
}
__device__ __forceinline__ float bf16_residual(float v) {
    return v - __bfloat162float(__float2bfloat16_rn(v));
}
__device__ __forceinline__ void ldsm_x4(uint32_t* r, uint32_t addr) {
    asm volatile("ldmatrix.sync.aligned.m8n8.x4.shared.b16 {%0,%1,%2,%3}, [%4];"
                 : "=r"(r[0]), "=r"(r[1]), "=r"(r[2]), "=r"(r[3]) : "r"(addr));
}
__device__ __forceinline__ void ldsm_x2(uint32_t* r, uint32_t addr) {
    asm volatile("ldmatrix.sync.aligned.m8n8.x2.shared.b16 {%0,%1}, [%2];"
                 : "=r"(r[0]), "=r"(r[1]) : "r"(addr));
}
__device__ __forceinline__ void mma16816(float* c, const uint32_t* a, const uint32_t* b) {
    asm volatile(
        "mma.sync.aligned.m16n8k16.row.col.f32.bf16.bf16.f32 "
        "{%0,%1,%2,%3}, {%4,%5,%6,%7}, {%8,%9}, {%0,%1,%2,%3};"
        : "+f"(c[0]), "+f"(c[1]), "+f"(c[2]), "+f"(c[3])
        : "r"(a[0]), "r"(a[1]), "r"(a[2]), "r"(a[3]), "r"(b[0]), "r"(b[1]));
}
__device__ __forceinline__ void cpasync16(uint32_t s, const void* g) {
    asm volatile("cp.async.ca.shared.global [%0], [%1], 16;" :: "r"(s), "l"(g));
}
__device__ __forceinline__ float sigmoidf_fast(float z) {
    return __fdividef(1.f, 1.f + __expf(-z));
}

// ---------------------------------------------------------------------------
// prep: W -> bf16 hi/lo tiles, coalesced. 32 blocks (8 per matrix).
// ---------------------------------------------------------------------------
__global__ void __launch_bounds__(256) prep_w_kernel(
    const float* __restrict__ Wk, const float* __restrict__ Wq,
    const float* __restrict__ Wv, const float* __restrict__ Wsk)
{
    const int m = blockIdx.x >> 3;
    const int chunk = blockIdx.x & 7;
    const float* W;
    switch (m) {
        case 0:  W = Wk;  break;
        case 1:  W = Wq;  break;
        case 2:  W = Wv;  break;
        default: W = Wsk; break;
    }
    __nv_bfloat16* hi = g_Wb + m * WB_ELEMS;
    __nv_bfloat16* lo = hi + TILE_ELEMS;

    #pragma unroll
    for (int it = 0; it < 2; it++) {
        int pos = chunk * 512 + threadIdx.x + 256 * it;
        int n  = pos >> 5;
        int k0 = (pos & 31) << 2;
        float w0 = W[(size_t)(k0 + 0) * D + n];
        float w1 = W[(size_t)(k0 + 1) * D + n];
        float w2 = W[(size_t)(k0 + 2) * D + n];
        float w3 = W[(size_t)(k0 + 3) * D + n];
        int e = n * ASTRIDE + k0;
        *(uint2*)(hi + e) = make_uint2(pack2(w0, w1), pack2(w2, w3));
        *(uint2*)(lo + e) = make_uint2(pack2(bf16_residual(w0), bf16_residual(w1)),
                                       pack2(bf16_residual(w2), bf16_residual(w3)));
    }
}

// ---------------------------------------------------------------------------
// Fused HMMA GEMM (R12 form). bf16 hi/lo split:
//   K, Q  : 2 passes — x-rounding damped by sigmoid
//   V, skip: 3 passes — linear in output
// K/Q/V stored fp16; skip stored fp32 into out (plain store).
// ---------------------------------------------------------------------------
__global__ void __launch_bounds__(256) gemm_fused_kernel(
    const float* __restrict__ x, int N,
    const float* __restrict__ bk, const float* __restrict__ bq,
    const float* __restrict__ bv, const float* __restrict__ bsk,
    float* __restrict__ out)
{
    extern __shared__ __nv_bfloat16 sm[];
    const uint32_t sbase = smem_u32(sm);

    const int tid  = threadIdx.x;
    const int wid  = tid >> 5;
    const int lane = tid & 31;
    const int m0   = blockIdx.x * TILE_M;
    const int rem  = N - m0;

    {
        const char* gsrc = (const char*)g_Wb;
        uint32_t sdst = sbase + SM_B0 * 2;
        #pragma unroll
        for (int i = 0; i < 17; i++) {
            uint32_t off = (uint32_t)(tid + 256 * i) * 16;
            cpasync16(sdst + off, gsrc + off);
        }
        asm volatile("cp.async.commit_group;");
    }

    {
        const float4* x4 = (const float4*)(x + (size_t)m0 * D);
        #pragma unroll
        for (int i = 0; i < 16; i++) {
            int idx = tid + 256 * i;
            int row = idx >> 5;
            int k4  = (idx & 31) << 2;
            float4 v = make_float4(0.f, 0.f, 0.f, 0.f);
            if (row < rem) v = x4[idx];
            uint2 hi = make_uint2(pack2(v.x, v.y), pack2(v.z, v.w));
            uint2 lo = make_uint2(pack2(bf16_residual(v.x), bf16_residual(v.y)),
                                  pack2(bf16_residual(v.z), bf16_residual(v.w)));
            int e = row * ASTRIDE + k4;
            *(uint2*)(sm + SM_A_HI + e) = hi;
            *(uint2*)(sm + SM_A_LO + e) = lo;
        }
    }

    const int mw = (wid & 1) << 6;
    const int nw = (wid >> 1) << 5;
    const int arow = lane & 15;
    const int acol = (lane >> 4) << 3;
    const int brow = lane & 7;
    const int bcol = ((lane >> 3) & 1) << 3;
    const int gid  = lane >> 2;
    const int tg   = lane & 3;

    const float* const bias[4] = { bk, bq, bv, bsk };

    #pragma unroll
    for (int mi = 0; mi < 4; mi++) {
        if (mi < 3) {
            const char* gsrc = (const char*)(g_Wb + (mi + 1) * WB_ELEMS);
            uint32_t sdst = sbase + (((mi + 1) & 1) ? SM_B1 : SM_B0) * 2;
            #pragma unroll
            for (int i = 0; i < 17; i++) {
                uint32_t off = (uint32_t)(tid + 256 * i) * 16;
                cpasync16(sdst + off, gsrc + off);
            }
            asm volatile("cp.async.commit_group;");
            asm volatile("cp.async.wait_group 1;");
        } else {
            asm volatile("cp.async.wait_group 0;");
        }
        __syncthreads();

        const uint32_t bHI = sbase + (((mi & 1) ? SM_B1 : SM_B0)) * 2;
        const uint32_t bLO = bHI + TILE_ELEMS * 2;
        const bool fullfix = (mi >= 2);   // V, skip get the Al*Bh pass

        float acc[4][4][4];
        #pragma unroll
        for (int i = 0; i < 4; i++)
            #pragma unroll
            for (int j = 0; j < 4; j++)
                #pragma unroll
                for (int k = 0; k < 4; k++) acc[i][j][k] = 0.f;

        #pragma unroll 1
        for (int ks = 0; ks < 8; ks++) {
            const int kk = ks << 4;
            uint32_t ah[4][4], al[4][4], bh[4][2], bl[4][2];
            #pragma unroll
            for (int mt = 0; mt < 4; mt++) {
                uint32_t off = (uint32_t)((mw + (mt << 4) + arow) * ASTRIDE + kk + acol) * 2;
                ldsm_x4(ah[mt], sbase + SM_A_HI * 2 + off);
                if (fullfix) ldsm_x4(al[mt], sbase + SM_A_LO * 2 + off);
            }
            #pragma unroll
            for (int nt = 0; nt < 4; nt++) {
                uint32_t off = (uint32_t)((nw + (nt << 3) + brow) * ASTRIDE + kk + bcol) * 2;
                ldsm_x2(bh[nt], bHI + off);
                ldsm_x2(bl[nt], bLO + off);
            }
            #pragma unroll
            for (int mt = 0; mt < 4; mt++)
                #pragma unroll
                for (int nt = 0; nt < 4; nt++) {
                    mma16816(acc[mt][nt], ah[mt], bh[nt]);
                    mma16816(acc[mt][nt], ah[mt], bl[nt]);
                    if (fullfix) mma16816(acc[mt][nt], al[mt], bh[nt]);
                }
        }

        // epilogue: add bias; K/Q/V -> fp16, skip -> fp32 into out
        {
            const float* b = bias[mi];
            #pragma unroll
            for (int mt = 0; mt < 4; mt++) {
                #pragma unroll
                for (int nt = 0; nt < 4; nt++) {
                    int col = nw + (nt << 3) + (tg << 1);
                    float2 bb = *(const float2*)(b + col);
                    int r0 = mw + (mt << 4) + gid;
                    int r1 = r0 + 8;
                    float2 u0, u1;
                    u0.x = acc[mt][nt][0] + bb.x; u0.y = acc[mt][nt][1] + bb.y;
                    u1.x = acc[mt][nt][2] + bb.x; u1.y = acc[mt][nt][3] + bb.y;
                    if (mi == 3) {
                        if (m0 + r0 < N) *(float2*)(out + (size_t)(m0 + r0) * D + col) = u0;
                        if (m0 + r1 < N) *(float2*)(out + (size_t)(m0 + r1) * D + col) = u1;
                    } else if (mi == 0) {
                        if (m0 + r0 < N)
                            *(__half2*)(g_Kh + (size_t)(m0 + r0) * D + col) =
                                __floats2half2_rn(u0.x, u0.y);
                        if (m0 + r1 < N)
                            *(__half2*)(g_Kh + (size_t)(m0 + r1) * D + col) =
                                __floats2half2_rn(u1.x, u1.y);
                    } else {
                        const int co = (mi == 1) ? 0 : D;   // q at 0, v at 128
                        if (m0 + r0 < N)
                            *(__half2*)(g_QVh + (size_t)(m0 + r0) * 2 * D + co + col) =
                                __floats2half2_rn(u0.x, u0.y);
                        if (m0 + r1 < N)
                            *(__half2*)(g_QVh + (size_t)(m0 + r1) * 2 * D + co + col) =
                                __floats2half2_rn(u1.x, u1.y);
                    }
                }
            }
        }
        __syncthreads();
    }
}

// ---------------------------------------------------------------------------
// Sort chain (side stream): zero -> convert+hist -> scan -> apply -> scatter
// ---------------------------------------------------------------------------
__global__ void __launch_bounds__(256) zero_cnt_kernel(int N)
{
    int i = blockIdx.x * blockDim.x + threadIdx.x;
    if (i < N) g_cnt[i] = 0;
}

__global__ void __launch_bounds__(256) convhist_kernel(
    const void* __restrict__ ei_raw, int E)
{
    const int idx  = blockIdx.x * blockDim.x + threadIdx.x;
    const int lane = threadIdx.x & 31;

    const int* raw = (const int*)ei_raw;
    unsigned nz = __ballot_sync(0xffffffffu,
                                (lane < 16) ? (raw[2 * lane + 1] != 0) : false);
    const bool is64 = (nz == 0u);

    if (idx < E) {
        int s, d;
        if (is64) {
            const long long* e64 = (const long long*)ei_raw;
            s = (int)e64[idx];
            d = (int)e64[(size_t)E + idx];
        } else {
            s = raw[idx];
            d = raw[(size_t)E + idx];
        }
        g_srcA[idx] = s;
        g_dstA[idx] = d;
        atomicAdd(&g_cnt[d], 1);
    }
}

__global__ void __launch_bounds__(1024) scan1_kernel(int N)
{
    __shared__ int s[1024];
    const int tid = threadIdx.x;
    const int i = blockIdx.x * 1024 + tid;
    int v = (i < N) ? g_cnt[i] : 0;
    s[tid] = v;
    __syncthreads();
    #pragma unroll
    for (int off = 1; off < 1024; off <<= 1) {
        int t = (tid >= off) ? s[tid - off] : 0;
        __syncthreads();
        s[tid] += t;
        __syncthreads();
    }
    if (i <= N) g_off[i] = s[tid] - v;
    if (tid == 1023) g_bsum[blockIdx.x] = s[1023];
}

__global__ void __launch_bounds__(1024) scan_apply_kernel(int N, int E)
{
    __shared__ int bpre_s;
    const int tid = threadIdx.x;
    if (tid < 32) {
        int v = 0;
        for (int b = tid; b < blockIdx.x; b += 32) v += g_bsum[b];
        #pragma unroll
        for (int o = 16; o > 0; o >>= 1) v += __shfl_down_sync(0xffffffffu, v, o);
        if (tid == 0) bpre_s = v;
    }
    __syncthreads();
    const int bpre = bpre_s;
    const int i = blockIdx.x * 1024 + tid;
    if (i < N) {
        int o = g_off[i] + bpre;
        g_off[i] = o;
        g_cur[i] = o;
    }
    if (i == 0) g_off[N] = E;
}

__global__ void __launch_bounds__(256) scatter_kernel(int E)
{
    int idx = blockIdx.x * blockDim.x + threadIdx.x;
    if (idx < E) {
        int d = g_dstA[idx];
        int p = atomicAdd(&g_cur[d], 1);
        g_ss[p] = g_srcA[idx];
    }
}

// ---------------------------------------------------------------------------
// Aggregate: one warp per dst node. Src indices for the whole segment are
// loaded ONCE via a lane-parallel coalesced load + __shfl (removes the
// per-iteration ss-load -> gather serial chain). x2 unroll, MUFU sigmoid,
// fp16 K/QV, red.add emission onto out (already holds skip).
// ---------------------------------------------------------------------------
__global__ void __launch_bounds__(256) edge_agg_kernel(int N, float* __restrict__ out)
{
    const int node = (blockIdx.x * blockDim.x + threadIdx.x) >> 5;
    const int lane = threadIdx.x & 31;
    if (node >= N) return;

    const int e0 = g_off[node];
    const int e1 = g_off[node + 1];
    const int deg = e1 - e0;
    if (deg == 0) return;

    // one coalesced vector load of up to 32 src indices for this segment
    int s_all = 0;
    if (lane < deg && lane < 32) s_all = g_ss[e0 + lane];

    float4 kd;
    {
        uint2 uk = *(const uint2*)(g_Kh + (size_t)node * D + 4 * lane);
        float2 ka = __half22float2(*(__half2*)&uk.x);
        float2 kb = __half22float2(*(__half2*)&uk.y);
        kd = make_float4(ka.x, ka.y, kb.x, kb.y);
    }
    float4 acc = make_float4(0.f, 0.f, 0.f, 0.f);

    const int degc = (deg < 32) ? deg : 32;
    int j = 0;
    #pragma unroll 1
    for (; j + 2 <= degc; j += 2) {
        int s0 = __shfl_sync(0xffffffffu, s_all, j);
        int s1 = __shfl_sync(0xffffffffu, s_all, j + 1);
        const __half* r0 = g_QVh + (size_t)s0 * 2 * D;
        const __half* r1 = g_QVh + (size_t)s1 * 2 * D;
        uint2 uq0 = *(const uint2*)(r0 + 4 * lane);
        uint2 uv0 = *(const uint2*)(r0 + D + 4 * lane);
        uint2 uq1 = *(const uint2*)(r1 + 4 * lane);
        uint2 uv1 = *(const uint2*)(r1 + D + 4 * lane);
        float2 qa0 = __half22float2(*(__half2*)&uq0.x), qb0 = __half22float2(*(__half2*)&uq0.y);
        float2 va0 = __half22float2(*(__half2*)&uv0.x), vb0 = __half22float2(*(__half2*)&uv0.y);
        float2 qa1 = __half22float2(*(__half2*)&uq1.x), qb1 = __half22float2(*(__half2*)&uq1.y);
        float2 va1 = __half22float2(*(__half2*)&uv1.x), vb1 = __half22float2(*(__half2*)&uv1.y);
        acc.x += va0.x * sigmoidf_fast(kd.x + qa0.x) + va1.x * sigmoidf_fast(kd.x + qa1.x);
        acc.y += va0.y * sigmoidf_fast(kd.y + qa0.y) + va1.y * sigmoidf_fast(kd.y + qa1.y);
        acc.z += vb0.x * sigmoidf_fast(kd.z + qb0.x) + vb1.x * sigmoidf_fast(kd.z + qb1.x);
        acc.w += vb0.y * sigmoidf_fast(kd.w + qb0.y) + vb1.y * sigmoidf_fast(kd.w + qb1.y);
    }
    if (j < degc) {
        int s0 = __shfl_sync(0xffffffffu, s_all, j);
        const __half* r0 = g_QVh + (size_t)s0 * 2 * D;
        uint2 uq0 = *(const uint2*)(r0 + 4 * lane);
        uint2 uv0 = *(const uint2*)(r0 + D + 4 * lane);
        float2 qa0 = __half22float2(*(__half2*)&uq0.x), qb0 = __half22float2(*(__half2*)&uq0.y);
        float2 va0 = __half22float2(*(__half2*)&uv0.x), vb0 = __half22float2(*(__half2*)&uv0.y);
        acc.x += va0.x * sigmoidf_fast(kd.x + qa0.x);
        acc.y += va0.y * sigmoidf_fast(kd.y + qa0.y);
        acc.z += vb0.x * sigmoidf_fast(kd.z + qb0.x);
        acc.w += vb0.y * sigmoidf_fast(kd.w + qb0.y);
    }
    // rare tail: degree > 32 (negligible probability at mean 6.4, but correct)
    #pragma unroll 1
    for (int e = e0 + 32; e < e1; e++) {
        int s0 = g_ss[e];
        const __half* r0 = g_QVh + (size_t)s0 * 2 * D;
        uint2 uq0 = *(const uint2*)(r0 + 4 * lane);
        uint2 uv0 = *(const uint2*)(r0 + D + 4 * lane);
        float2 qa0 = __half22float2(*(__half2*)&uq0.x), qb0 = __half22float2(*(__half2*)&uq0.y);
        float2 va0 = __half22float2(*(__half2*)&uv0.x), vb0 = __half22float2(*(__half2*)&uv0.y);
        acc.x += va0.x * sigmoidf_fast(kd.x + qa0.x);
        acc.y += va0.y * sigmoidf_fast(kd.y + qa0.y);
        acc.z += vb0.x * sigmoidf_fast(kd.z + qb0.x);
        acc.w += vb0.y * sigmoidf_fast(kd.w + qb0.y);
    }

    float* p = out + (size_t)node * D + lane * 4;
    asm volatile("red.global.add.v4.f32 [%0], {%1, %2, %3, %4};"
                 :: "l"(p), "f"(acc.x), "f"(acc.y), "f"(acc.z), "f"(acc.w)
                 : "memory");
}

// ---------------------------------------------------------------------------
extern "C" void kernel_launch(void* const* d_in, const int* in_sizes, int n_in,
                              void* d_out, int out_size)
{
    const float* x    = (const float*)d_in[0];
    const void*  ei   = d_in[1];
    const float* Wk   = (const float*)d_in[3];
    const float* bk   = (const float*)d_in[4];
    const float* Wq   = (const float*)d_in[5];
    const float* bq   = (const float*)d_in[6];
    const float* Wv   = (const float*)d_in[7];
    const float* bv   = (const float*)d_in[8];
    const float* Wsk  = (const float*)d_in[9];
    const float* bias = (const float*)d_in[10];
    float* out = (float*)d_out;

    const int N = in_sizes[0] / D;
    const int E = in_sizes[1] / 2;

    cudaFuncSetAttribute(gemm_fused_kernel,
                         cudaFuncAttributeMaxDynamicSharedMemorySize, SM_BYTES);

    cudaStream_t s2;
    cudaStreamCreateWithFlags(&s2, cudaStreamNonBlocking);
    cudaEvent_t evFork, evJoin;
    cudaEventCreateWithFlags(&evFork, cudaEventDisableTiming);
    cudaEventCreateWithFlags(&evJoin, cudaEventDisableTiming);

    cudaEventRecord(evFork, 0);
    cudaStreamWaitEvent(s2, evFork, 0);

    // branch B (side stream): edge sort chain
    zero_cnt_kernel<<<(N + 255) / 256, 256, 0, s2>>>(N);
    convhist_kernel<<<(E + 255) / 256, 256, 0, s2>>>(ei, E);
    const int nb = (N + 1023) / 1024;
    scan1_kernel<<<nb, 1024, 0, s2>>>(N);
    scan_apply_kernel<<<nb, 1024, 0, s2>>>(N, E);
    scatter_kernel<<<(E + 255) / 256, 256, 0, s2>>>(E);
    cudaEventRecord(evJoin, s2);

    // branch A (main stream): projections (skip written to out here)
    prep_w_kernel<<<32, 256>>>(Wk, Wq, Wv, Wsk);
    gemm_fused_kernel<<<(N + TILE_M - 1) / TILE_M, 256, SM_BYTES>>>(
        x, N, bk, bq, bv, bias, out);

    // join, then aggregate (red.add onto skip)
    cudaStreamWaitEvent(0, evJoin, 0);
    edge_agg_kernel<<<(N * 32 + 255) / 256, 256>>>(N, out);

    cudaEventDestroy(evFork);
    cudaEventDestroy(evJoin);
    cudaStreamDestroy(s2);
}